// round 14
// baseline (speedup 1.0000x reference)
#include <cuda_runtime.h>
#include <cuda_fp16.h>
#include <math.h>

#define BB 4
#define CC 64
#define HH 128
#define WW 128
#define OO 64
#define NKK 9
#define QDIM 576
#define NPIX (BB*HH*WW)     // 65536

typedef unsigned int u32;

// ---- device scratch ----
__device__ float g_xT[BB*HH*WW*CC];             // NHWC x
__device__ float g_params[27*NPIX];             // planar [co][pix]
__device__ __half g_wb[NKK*OO*CC];              // main weights fp16, [kk][o][c]
__device__ __half g_wpg[NKK*32*CC];             // pg weights fp16, [kk][co32][c]

__device__ __forceinline__ u32 smem_u32(const void* p) {
    u32 a;
    asm("{ .reg .u64 t; cvta.to.shared.u64 t, %1; cvt.u32.u64 %0, t; }" : "=r"(a) : "l"(p));
    return a;
}

#define LDSM4(r0, r1, r2, r3, addr) \
    asm volatile("ldmatrix.sync.aligned.m8n8.x4.shared.b16 {%0,%1,%2,%3},[%4];" \
        : "=r"(r0), "=r"(r1), "=r"(r2), "=r"(r3) : "r"(addr))

__device__ __forceinline__ void mma16816(float* d, u32 a0, u32 a1, u32 a2, u32 a3,
                                         u32 b0, u32 b1) {
    asm volatile(
        "mma.sync.aligned.m16n8k16.row.col.f32.f16.f16.f32 "
        "{%0,%1,%2,%3},{%4,%5,%6,%7},{%8,%9},{%0,%1,%2,%3};"
        : "+f"(d[0]), "+f"(d[1]), "+f"(d[2]), "+f"(d[3])
        : "r"(a0), "r"(a1), "r"(a2), "r"(a3), "r"(b0), "r"(b1));
}

__device__ __forceinline__ void h2_store(unsigned char* dst,
                                         float v0, float v1, float v2, float v3) {
    __half2 a = __floats2half2_rn(v0, v1);
    __half2 b = __floats2half2_rn(v2, v3);
    *(uint2*)dst = make_uint2(*(u32*)&a, *(u32*)&b);
}

// ============================================================
// Kernel 0: x NCHW -> NHWC
// ============================================================
__global__ void k_transpose_x(const float* __restrict__ x) {
    __shared__ float tile[64][129];
    int bh = blockIdx.x;
    int b = bh >> 7, h = bh & 127;
    int t = threadIdx.x;
    for (int i = t; i < 64 * 128; i += 256) {
        int c = i >> 7, w = i & 127;
        tile[c][w] = x[((size_t)(b * CC + c) * HH + h) * WW + w];
    }
    __syncthreads();
    for (int i = t; i < 64 * 128; i += 256) {
        int w = i >> 6, c = i & 63;
        g_xT[((size_t)bh * WW + w) * CC + c] = tile[c][w];
    }
}

// ============================================================
// Kernel 1: merged weight prep (fp16)
// ============================================================
__global__ void k_prep_w(const float* __restrict__ wgt,
                         const float* __restrict__ pgw) {
    int i = blockIdx.x * 256 + threadIdx.x;
    if (i < NKK * OO * CC) {                       // 36864
        int kk = i % 9;
        int c  = (i / 9) & 63;
        int o  = i / (9 * 64);
        g_wb[(kk * OO + o) * CC + c] = __float2half(wgt[i]);
    }
    int j = i - NKK * OO * CC;
    if (j >= 0 && j < NKK * 32 * CC) {             // 18432
        int c  = j & 63;
        int co = (j >> 6) & 31;
        int kk = j >> 11;
        float w = (co < 27) ? pgw[co * QDIM + c * 9 + kk] : 0.f;
        g_wpg[j] = __float2half(w);
    }
}

// ============================================================
// MMA constants
// ============================================================
#define APITCH 72                    // fp16/row (144 B)
#define ROWB (APITCH*2)              // 144
#define A_BYTES (64 * ROWB)          // 9216
#define DPITCH 68

// ============================================================
// Kernel 2: offset/mask conv (R12 exact — measured 24.0us)
// smem: A@0 (9216), B@9216 (4608) -> 13824
// ============================================================
#define P_OFF_B 9216
#define P_SMEM  13824

__global__ void __launch_bounds__(128) k_params(const float* __restrict__ pgb) {
    __shared__ __align__(16) unsigned char blob[P_SMEM];
    u32 S = smem_u32(blob);
    int t = threadIdx.x;
    int lane = t & 31;
    int warp = t >> 5;
    int blk = blockIdx.x;            // 1024
    int wb = (blk & 1) * 64;
    int bh = blk >> 1;
    int b = bh >> 7, h = bh & 127;

    const float* xb = &g_xT[(size_t)b * HH * WW * CC];

    float acc[4][4];
#pragma unroll
    for (int j = 0; j < 4; j++)
#pragma unroll
        for (int r = 0; r < 4; r++) acc[j][r] = 0.f;

    u32 aRow = (u32)((warp * 16 + (lane & 15)) * ROWB) + (u32)((lane >> 4) * 16);
    u32 bRowSel = (u32)(((lane & 7) + ((lane >> 4) & 1) * 8) * ROWB)
                  + (u32)(((lane >> 3) & 1) * 16);

#pragma unroll 1
    for (int kk = 0; kk < NKK; kk++) {
        int dh = kk / 3 - 1, dw = kk % 3 - 1;
        int hh = h + dh;
        __syncthreads();             // prev MMA reads done
        // ---- stage A: shifted patch 64 px x 64 c, fp16 ----
#pragma unroll
        for (int it = 0; it < 8; it++) {
            int idx = it * 128 + t;
            int c4 = idx & 15;
            int px = idx >> 4;
            int gw = wb + px + dw;
            float4 g = make_float4(0.f, 0.f, 0.f, 0.f);
            if (hh >= 0 && hh < HH && gw >= 0 && gw < WW)
                g = __ldg((const float4*)&xb[((size_t)hh * WW + gw) * CC + c4 * 4]);
            h2_store(blob + px * ROWB + c4 * 8, g.x, g.y, g.z, g.w);
        }
        // ---- stage B: 32 co x 64 c fp16 (256 uint4) ----
        {
            const uint4* gh = (const uint4*)&g_wpg[(size_t)kk * 32 * CC];
#pragma unroll
            for (int it = 0; it < 2; it++) {
                int idx = it * 128 + t;
                int row = idx >> 3;
                int col = idx & 7;
                *(uint4*)(blob + P_OFF_B + row * ROWB + col * 16) = __ldg(&gh[idx]);
            }
        }
        __syncthreads();
        // ---- MMA: 4 ksteps x 2 n-pairs ----
#pragma unroll
        for (int ks = 0; ks < 4; ks++) {
            u32 aa = S + aRow + ks * 32;
            u32 a0, a1, a2, a3;
            LDSM4(a0, a1, a2, a3, aa);
#pragma unroll
            for (int np = 0; np < 2; np++) {
                u32 ba = S + P_OFF_B + (u32)(np * 16 * ROWB) + bRowSel + ks * 32;
                u32 b0, b1, b2, b3;
                LDSM4(b0, b1, b2, b3, ba);
                mma16816(acc[np * 2 + 0], a0, a1, a2, a3, b0, b1);
                mma16816(acc[np * 2 + 1], a0, a1, a2, a3, b2, b3);
            }
        }
    }

    // ---- epilogue: stage sD[32co][68px], planar coalesced write ----
    __syncthreads();
    float* sD = (float*)blob;
    {
        int px0 = warp * 16 + (lane >> 2);
#pragma unroll
        for (int j = 0; j < 4; j++) {
            int co = j * 8 + 2 * (lane & 3);
            sD[co * DPITCH + px0]           = acc[j][0];
            sD[(co + 1) * DPITCH + px0]     = acc[j][1];
            sD[co * DPITCH + px0 + 8]       = acc[j][2];
            sD[(co + 1) * DPITCH + px0 + 8] = acc[j][3];
        }
    }
    __syncthreads();
#pragma unroll
    for (int i = 0; i < 14; i++) {
        int idx = i * 128 + t;               // 27*64 = 1728
        if (idx < 1728) {
            int co = idx >> 6;
            int px = idx & 63;
            g_params[(size_t)co * NPIX + (size_t)bh * WW + wb + px] =
                sD[co * DPITCH + px] + __ldg(&pgb[co]);
        }
    }
}

// ============================================================
// Kernel 3: fused gather + MMA (R13 pipeline + B reg-prefetch)
// smem: A0@0, A1@9216, B@18432 (9216), pw@27648 [2][4][64],
//       pi@29696 [2][4][64] -> 31744
// ============================================================
#define M_OFF_B  18432
#define M_OFF_PW 27648
#define M_OFF_PI 29696
#define M_SMEM   31744

__device__ __forceinline__ void m_params(unsigned char* blob, int t, int wb,
                                         int bh, int h, int kt, int slot) {
    if (t >= 64) return;
    float* pw = (float*)(blob + M_OFF_PW) + slot * 256;
    int*   pi = (int*)(blob + M_OFF_PI) + slot * 256;
    int px = t;
    int w = wb + px;
    size_t pixi = (size_t)bh * WW + w;
    float dy = __ldg(&g_params[(size_t)(2 * kt) * NPIX + pixi]);
    float dx = __ldg(&g_params[(size_t)(2 * kt + 1) * NPIX + pixi]);
    float m  = __ldg(&g_params[(size_t)(18 + kt) * NPIX + pixi]);
    float mask = 1.f / (1.f + expf(-m));
    float ys = (float)(h - 1 + kt / 3) + dy;
    float xs = (float)(w - 1 + kt % 3) + dx;
    float y0f = floorf(ys), x0f = floorf(xs);
    float ly = ys - y0f, lx = xs - x0f;
    int y0 = (int)y0f, x0 = (int)x0f;
    float vy0 = (y0 >= 0 && y0 < HH) ? 1.f : 0.f;
    float vy1 = (y0 + 1 >= 0 && y0 + 1 < HH) ? 1.f : 0.f;
    float vx0 = (x0 >= 0 && x0 < WW) ? 1.f : 0.f;
    float vx1 = (x0 + 1 >= 0 && x0 + 1 < WW) ? 1.f : 0.f;
    pw[0 * 64 + px] = (1.f - ly) * (1.f - lx) * mask * vy0 * vx0;
    pw[1 * 64 + px] = (1.f - ly) * lx         * mask * vy0 * vx1;
    pw[2 * 64 + px] = ly * (1.f - lx)         * mask * vy1 * vx0;
    pw[3 * 64 + px] = ly * lx                 * mask * vy1 * vx1;
    pi[0 * 64 + px] = min(max(y0, 0), HH - 1) * WW;
    pi[1 * 64 + px] = min(max(y0 + 1, 0), HH - 1) * WW;
    pi[2 * 64 + px] = min(max(x0, 0), WW - 1);
    pi[3 * 64 + px] = min(max(x0 + 1, 0), WW - 1);
}

__device__ __forceinline__ void m_gather(unsigned char* blob, const float* xb,
                                         int t, int slot, u32 aOff) {
    const float* pw = (const float*)(blob + M_OFF_PW) + slot * 256;
    const int*   pi = (const int*)(blob + M_OFF_PI) + slot * 256;
#pragma unroll
    for (int it = 0; it < 8; it++) {
        int idx = it * 128 + t;
        int c4 = idx & 15;
        int px = idx >> 4;
        float w00 = pw[0 * 64 + px];
        float w01 = pw[1 * 64 + px];
        float w10 = pw[2 * 64 + px];
        float w11 = pw[3 * 64 + px];
        int r0  = pi[0 * 64 + px];
        int r1  = pi[1 * 64 + px];
        int x0c = pi[2 * 64 + px];
        int x1c = pi[3 * 64 + px];
        float4 g00 = __ldg((const float4*)&xb[(size_t)(r0 + x0c) * CC + c4 * 4]);
        float4 g01 = __ldg((const float4*)&xb[(size_t)(r0 + x1c) * CC + c4 * 4]);
        float4 g10 = __ldg((const float4*)&xb[(size_t)(r1 + x0c) * CC + c4 * 4]);
        float4 g11 = __ldg((const float4*)&xb[(size_t)(r1 + x1c) * CC + c4 * 4]);
        float v0 = w00 * g00.x + w01 * g01.x + w10 * g10.x + w11 * g11.x;
        float v1 = w00 * g00.y + w01 * g01.y + w10 * g10.y + w11 * g11.y;
        float v2 = w00 * g00.z + w01 * g01.z + w10 * g10.z + w11 * g11.z;
        float v3 = w00 * g00.w + w01 * g01.w + w10 * g10.w + w11 * g11.w;
        h2_store(blob + aOff + px * ROWB + c4 * 8, v0, v1, v2, v3);
    }
}

__global__ void __launch_bounds__(128) k_main(const float* __restrict__ bias,
                                              float* __restrict__ out) {
    __shared__ __align__(16) unsigned char blob[M_SMEM];
    u32 S = smem_u32(blob);

    int t = threadIdx.x;
    int lane = t & 31;
    int warp = t >> 5;
    int blk = blockIdx.x;
    int wb = (blk & 1) * 64;
    int bh = blk >> 1;
    int b = bh >> 7, h = bh & 127;

    const float* xb = &g_xT[(size_t)b * HH * WW * CC];

    float acc[8][4];
#pragma unroll
    for (int j = 0; j < 8; j++)
#pragma unroll
        for (int r = 0; r < 4; r++) acc[j][r] = 0.f;

    u32 aRow = (u32)((warp * 16 + (lane & 15)) * ROWB) + (u32)((lane >> 4) * 16);
    u32 bRowSel = (u32)(((lane & 7) + ((lane >> 4) & 1) * 8) * ROWB)
                  + (u32)(((lane >> 3) & 1) * 16);
    // B staging addresses for this thread (4 uint4 per tap)
    int bRow0 = t >> 3;              // +32 per chunk of 128 thr... see loop
    int bCol0 = t & 7;

    // prologue: params(0) + gather(0) into A0; prefetch B(0)
    m_params(blob, t, wb, bh, h, 0, 0);
    __syncthreads();
    m_gather(blob, xb, t, 0, 0);
    uint4 bF[4];
    {
        const uint4* gh = (const uint4*)&g_wb[0];
#pragma unroll
        for (int it = 0; it < 4; it++) bF[it] = __ldg(&gh[it * 128 + t]);
    }

#pragma unroll 1
    for (int kk = 0; kk < NKK; kk++) {
        // ---- STS B(kk) from prefetched regs (serial region: STS only) ----
#pragma unroll
        for (int it = 0; it < 4; it++) {
            int row = bRow0 + it * 16;
            *(uint4*)(blob + M_OFF_B + row * ROWB + bCol0 * 16) = bF[it];
        }
        // ---- params(kk+1) into alt slot ----
        if (kk < 8) m_params(blob, t, wb, bh, h, kk + 1, (kk + 1) & 1);
        __syncthreads();             // A[kk&1], B(kk), params visible
        // ---- prefetch B(kk+1) (LDGs overlap MMA kk) ----
        if (kk < 8) {
            const uint4* gh = (const uint4*)&g_wb[(size_t)(kk + 1) * OO * CC];
#pragma unroll
            for (int it = 0; it < 4; it++) bF[it] = __ldg(&gh[it * 128 + t]);
        }
        // ---- gather(kk+1) into alt A buffer (overlaps MMA kk) ----
        if (kk < 8)
            m_gather(blob, xb, t, (kk + 1) & 1, (u32)(((kk + 1) & 1) * A_BYTES));
        // ---- MMA(kk) ----
        u32 aBase = S + (u32)((kk & 1) * A_BYTES) + aRow;
#pragma unroll
        for (int ks = 0; ks < 4; ks++) {
            u32 aa = aBase + ks * 32;
            u32 a0, a1, a2, a3;
            LDSM4(a0, a1, a2, a3, aa);
#pragma unroll
            for (int np = 0; np < 4; np++) {
                u32 ba = S + M_OFF_B + (u32)(np * 16 * ROWB) + bRowSel + ks * 32;
                u32 b0, b1, b2, b3;
                LDSM4(b0, b1, b2, b3, ba);
                mma16816(acc[np * 2 + 0], a0, a1, a2, a3, b0, b1);
                mma16816(acc[np * 2 + 1], a0, a1, a2, a3, b2, b3);
            }
        }
        __syncthreads();             // MMA(kk) + gather(kk+1) done
    }

    // ---- epilogue: stage D in smem [o][px] (pitch 68), coalesced write ----
    float* sD = (float*)blob;        // 64*68*4 = 17408 <= 31744
    {
        int px0 = warp * 16 + (lane >> 2);
#pragma unroll
        for (int j = 0; j < 8; j++) {
            int o = j * 8 + 2 * (lane & 3);
            sD[o * DPITCH + px0]           = acc[j][0];
            sD[(o + 1) * DPITCH + px0]     = acc[j][1];
            sD[o * DPITCH + px0 + 8]       = acc[j][2];
            sD[(o + 1) * DPITCH + px0 + 8] = acc[j][3];
        }
    }
    __syncthreads();
    {
        int o = t >> 1;
        int half = t & 1;
        float bv = __ldg(&bias[o]);
        size_t base = ((size_t)(b * OO + o) * HH + h) * WW + wb + half * 32;
        const float* src = &sD[o * DPITCH + half * 32];
#pragma unroll
        for (int i = 0; i < 8; i++) {
            float4 v = *(const float4*)&src[i * 4];
            v.x += bv; v.y += bv; v.z += bv; v.w += bv;
            *(float4*)&out[base + i * 4] = v;
        }
    }
}

// ============================================================
extern "C" void kernel_launch(void* const* d_in, const int* in_sizes, int n_in,
                              void* d_out, int out_size) {
    const float* x      = (const float*)d_in[0];
    const float* weight = (const float*)d_in[1];
    const float* bias   = (const float*)d_in[2];
    const float* pg_w   = (const float*)d_in[3];
    const float* pg_b   = (const float*)d_in[4];
    float* out = (float*)d_out;

    k_transpose_x<<<BB * HH, 256>>>(x);
    k_prep_w<<<(NKK * OO * CC + NKK * 32 * CC + 255) / 256, 256>>>(weight, pg_w);
    k_params<<<BB * HH * 2, 128>>>(pg_b);
    k_main<<<BB * HH * 2, 128>>>(bias, out);
}

// round 15
// speedup vs baseline: 1.1722x; 1.1722x over previous
#include <cuda_runtime.h>
#include <cuda_fp16.h>
#include <math.h>

#define BB 4
#define CC 64
#define HH 128
#define WW 128
#define OO 64
#define NKK 9
#define QDIM 576
#define NPIX (BB*HH*WW)     // 65536

typedef unsigned int u32;

// ---- device scratch ----
__device__ float g_xT[BB*HH*WW*CC];             // NHWC x
__device__ float g_params[27*NPIX];             // planar [co][pix]
__device__ __half g_wb[NKK*OO*CC];              // main weights fp16, [kk][o][c]
__device__ __half g_wpg[NKK*32*CC];             // pg weights fp16, [kk][co32][c]

__device__ __forceinline__ u32 smem_u32(const void* p) {
    u32 a;
    asm("{ .reg .u64 t; cvta.to.shared.u64 t, %1; cvt.u32.u64 %0, t; }" : "=r"(a) : "l"(p));
    return a;
}

#define LDSM4(r0, r1, r2, r3, addr) \
    asm volatile("ldmatrix.sync.aligned.m8n8.x4.shared.b16 {%0,%1,%2,%3},[%4];" \
        : "=r"(r0), "=r"(r1), "=r"(r2), "=r"(r3) : "r"(addr))

__device__ __forceinline__ void mma16816(float* d, u32 a0, u32 a1, u32 a2, u32 a3,
                                         u32 b0, u32 b1) {
    asm volatile(
        "mma.sync.aligned.m16n8k16.row.col.f32.f16.f16.f32 "
        "{%0,%1,%2,%3},{%4,%5,%6,%7},{%8,%9},{%0,%1,%2,%3};"
        : "+f"(d[0]), "+f"(d[1]), "+f"(d[2]), "+f"(d[3])
        : "r"(a0), "r"(a1), "r"(a2), "r"(a3), "r"(b0), "r"(b1));
}

__device__ __forceinline__ void h2_store(unsigned char* dst,
                                         float v0, float v1, float v2, float v3) {
    __half2 a = __floats2half2_rn(v0, v1);
    __half2 b = __floats2half2_rn(v2, v3);
    *(uint2*)dst = make_uint2(*(u32*)&a, *(u32*)&b);
}

// ============================================================
// Kernel 0: x NCHW -> NHWC
// ============================================================
__global__ void k_transpose_x(const float* __restrict__ x) {
    __shared__ float tile[64][129];
    int bh = blockIdx.x;
    int b = bh >> 7, h = bh & 127;
    int t = threadIdx.x;
    for (int i = t; i < 64 * 128; i += 256) {
        int c = i >> 7, w = i & 127;
        tile[c][w] = x[((size_t)(b * CC + c) * HH + h) * WW + w];
    }
    __syncthreads();
    for (int i = t; i < 64 * 128; i += 256) {
        int w = i >> 6, c = i & 63;
        g_xT[((size_t)bh * WW + w) * CC + c] = tile[c][w];
    }
}

// ============================================================
// Kernel 1: merged weight prep (fp16)
// ============================================================
__global__ void k_prep_w(const float* __restrict__ wgt,
                         const float* __restrict__ pgw) {
    int i = blockIdx.x * 256 + threadIdx.x;
    if (i < NKK * OO * CC) {                       // 36864
        int kk = i % 9;
        int c  = (i / 9) & 63;
        int o  = i / (9 * 64);
        g_wb[(kk * OO + o) * CC + c] = __float2half(wgt[i]);
    }
    int j = i - NKK * OO * CC;
    if (j >= 0 && j < NKK * 32 * CC) {             // 18432
        int c  = j & 63;
        int co = (j >> 6) & 31;
        int kk = j >> 11;
        float w = (co < 27) ? pgw[co * QDIM + c * 9 + kk] : 0.f;
        g_wpg[j] = __float2half(w);
    }
}

// ============================================================
// MMA constants
// ============================================================
#define APITCH 72                    // fp16/row (144 B)
#define ROWB (APITCH*2)              // 144
#define A_BYTES (64 * ROWB)          // 9216
#define DPITCH 68

// ============================================================
// Kernel 2: offset/mask conv (R12 exact — measured 24.0us)
// smem: A@0 (9216), B@9216 (4608) -> 13824
// ============================================================
#define P_OFF_B 9216
#define P_SMEM  13824

__global__ void __launch_bounds__(128) k_params(const float* __restrict__ pgb) {
    __shared__ __align__(16) unsigned char blob[P_SMEM];
    u32 S = smem_u32(blob);
    int t = threadIdx.x;
    int lane = t & 31;
    int warp = t >> 5;
    int blk = blockIdx.x;            // 1024
    int wb = (blk & 1) * 64;
    int bh = blk >> 1;
    int b = bh >> 7, h = bh & 127;

    const float* xb = &g_xT[(size_t)b * HH * WW * CC];

    float acc[4][4];
#pragma unroll
    for (int j = 0; j < 4; j++)
#pragma unroll
        for (int r = 0; r < 4; r++) acc[j][r] = 0.f;

    u32 aRow = (u32)((warp * 16 + (lane & 15)) * ROWB) + (u32)((lane >> 4) * 16);
    u32 bRowSel = (u32)(((lane & 7) + ((lane >> 4) & 1) * 8) * ROWB)
                  + (u32)(((lane >> 3) & 1) * 16);

#pragma unroll 1
    for (int kk = 0; kk < NKK; kk++) {
        int dh = kk / 3 - 1, dw = kk % 3 - 1;
        int hh = h + dh;
        __syncthreads();             // prev MMA reads done
        // ---- stage A: shifted patch 64 px x 64 c, fp16 ----
#pragma unroll
        for (int it = 0; it < 8; it++) {
            int idx = it * 128 + t;
            int c4 = idx & 15;
            int px = idx >> 4;
            int gw = wb + px + dw;
            float4 g = make_float4(0.f, 0.f, 0.f, 0.f);
            if (hh >= 0 && hh < HH && gw >= 0 && gw < WW)
                g = __ldg((const float4*)&xb[((size_t)hh * WW + gw) * CC + c4 * 4]);
            h2_store(blob + px * ROWB + c4 * 8, g.x, g.y, g.z, g.w);
        }
        // ---- stage B: 32 co x 64 c fp16 (256 uint4) ----
        {
            const uint4* gh = (const uint4*)&g_wpg[(size_t)kk * 32 * CC];
#pragma unroll
            for (int it = 0; it < 2; it++) {
                int idx = it * 128 + t;
                int row = idx >> 3;
                int col = idx & 7;
                *(uint4*)(blob + P_OFF_B + row * ROWB + col * 16) = __ldg(&gh[idx]);
            }
        }
        __syncthreads();
        // ---- MMA: 4 ksteps x 2 n-pairs ----
#pragma unroll
        for (int ks = 0; ks < 4; ks++) {
            u32 aa = S + aRow + ks * 32;
            u32 a0, a1, a2, a3;
            LDSM4(a0, a1, a2, a3, aa);
#pragma unroll
            for (int np = 0; np < 2; np++) {
                u32 ba = S + P_OFF_B + (u32)(np * 16 * ROWB) + bRowSel + ks * 32;
                u32 b0, b1, b2, b3;
                LDSM4(b0, b1, b2, b3, ba);
                mma16816(acc[np * 2 + 0], a0, a1, a2, a3, b0, b1);
                mma16816(acc[np * 2 + 1], a0, a1, a2, a3, b2, b3);
            }
        }
    }

    // ---- epilogue: stage sD[32co][68px], planar coalesced write ----
    __syncthreads();
    float* sD = (float*)blob;
    {
        int px0 = warp * 16 + (lane >> 2);
#pragma unroll
        for (int j = 0; j < 4; j++) {
            int co = j * 8 + 2 * (lane & 3);
            sD[co * DPITCH + px0]           = acc[j][0];
            sD[(co + 1) * DPITCH + px0]     = acc[j][1];
            sD[co * DPITCH + px0 + 8]       = acc[j][2];
            sD[(co + 1) * DPITCH + px0 + 8] = acc[j][3];
        }
    }
    __syncthreads();
#pragma unroll
    for (int i = 0; i < 14; i++) {
        int idx = i * 128 + t;               // 27*64 = 1728
        if (idx < 1728) {
            int co = idx >> 6;
            int px = idx & 63;
            g_params[(size_t)co * NPIX + (size_t)bh * WW + wb + px] =
                sD[co * DPITCH + px] + __ldg(&pgb[co]);
        }
    }
}

// ============================================================
// Kernel 3: fused gather + MMA (R13 exact — measured ~52us)
// smem: A0@0, A1@9216, B@18432 (9216), pw@27648 [2][4][64],
//       pi@29696 [2][4][64] -> 31744
// ============================================================
#define M_OFF_B  18432
#define M_OFF_PW 27648
#define M_OFF_PI 29696
#define M_SMEM   31744

__device__ __forceinline__ void m_params(unsigned char* blob, int t, int wb,
                                         int bh, int h, int kt, int slot) {
    if (t >= 64) return;
    float* pw = (float*)(blob + M_OFF_PW) + slot * 256;
    int*   pi = (int*)(blob + M_OFF_PI) + slot * 256;
    int px = t;
    int w = wb + px;
    size_t pixi = (size_t)bh * WW + w;
    float dy = __ldg(&g_params[(size_t)(2 * kt) * NPIX + pixi]);
    float dx = __ldg(&g_params[(size_t)(2 * kt + 1) * NPIX + pixi]);
    float m  = __ldg(&g_params[(size_t)(18 + kt) * NPIX + pixi]);
    float mask = 1.f / (1.f + expf(-m));
    float ys = (float)(h - 1 + kt / 3) + dy;
    float xs = (float)(w - 1 + kt % 3) + dx;
    float y0f = floorf(ys), x0f = floorf(xs);
    float ly = ys - y0f, lx = xs - x0f;
    int y0 = (int)y0f, x0 = (int)x0f;
    float vy0 = (y0 >= 0 && y0 < HH) ? 1.f : 0.f;
    float vy1 = (y0 + 1 >= 0 && y0 + 1 < HH) ? 1.f : 0.f;
    float vx0 = (x0 >= 0 && x0 < WW) ? 1.f : 0.f;
    float vx1 = (x0 + 1 >= 0 && x0 + 1 < WW) ? 1.f : 0.f;
    pw[0 * 64 + px] = (1.f - ly) * (1.f - lx) * mask * vy0 * vx0;
    pw[1 * 64 + px] = (1.f - ly) * lx         * mask * vy0 * vx1;
    pw[2 * 64 + px] = ly * (1.f - lx)         * mask * vy1 * vx0;
    pw[3 * 64 + px] = ly * lx                 * mask * vy1 * vx1;
    pi[0 * 64 + px] = min(max(y0, 0), HH - 1) * WW;
    pi[1 * 64 + px] = min(max(y0 + 1, 0), HH - 1) * WW;
    pi[2 * 64 + px] = min(max(x0, 0), WW - 1);
    pi[3 * 64 + px] = min(max(x0 + 1, 0), WW - 1);
}

__device__ __forceinline__ void m_gather(unsigned char* blob, const float* xb,
                                         int t, int slot, u32 aOff) {
    const float* pw = (const float*)(blob + M_OFF_PW) + slot * 256;
    const int*   pi = (const int*)(blob + M_OFF_PI) + slot * 256;
#pragma unroll
    for (int it = 0; it < 8; it++) {
        int idx = it * 128 + t;
        int c4 = idx & 15;
        int px = idx >> 4;
        float w00 = pw[0 * 64 + px];
        float w01 = pw[1 * 64 + px];
        float w10 = pw[2 * 64 + px];
        float w11 = pw[3 * 64 + px];
        int r0  = pi[0 * 64 + px];
        int r1  = pi[1 * 64 + px];
        int x0c = pi[2 * 64 + px];
        int x1c = pi[3 * 64 + px];
        float4 g00 = __ldg((const float4*)&xb[(size_t)(r0 + x0c) * CC + c4 * 4]);
        float4 g01 = __ldg((const float4*)&xb[(size_t)(r0 + x1c) * CC + c4 * 4]);
        float4 g10 = __ldg((const float4*)&xb[(size_t)(r1 + x0c) * CC + c4 * 4]);
        float4 g11 = __ldg((const float4*)&xb[(size_t)(r1 + x1c) * CC + c4 * 4]);
        float v0 = w00 * g00.x + w01 * g01.x + w10 * g10.x + w11 * g11.x;
        float v1 = w00 * g00.y + w01 * g01.y + w10 * g10.y + w11 * g11.y;
        float v2 = w00 * g00.z + w01 * g01.z + w10 * g10.z + w11 * g11.z;
        float v3 = w00 * g00.w + w01 * g01.w + w10 * g10.w + w11 * g11.w;
        h2_store(blob + aOff + px * ROWB + c4 * 8, v0, v1, v2, v3);
    }
}

__global__ void __launch_bounds__(128) k_main(const float* __restrict__ bias,
                                              float* __restrict__ out) {
    __shared__ __align__(16) unsigned char blob[M_SMEM];
    u32 S = smem_u32(blob);

    int t = threadIdx.x;
    int lane = t & 31;
    int warp = t >> 5;
    int blk = blockIdx.x;
    int wb = (blk & 1) * 64;
    int bh = blk >> 1;
    int b = bh >> 7, h = bh & 127;

    const float* xb = &g_xT[(size_t)b * HH * WW * CC];

    float acc[8][4];
#pragma unroll
    for (int j = 0; j < 8; j++)
#pragma unroll
        for (int r = 0; r < 4; r++) acc[j][r] = 0.f;

    u32 aRow = (u32)((warp * 16 + (lane & 15)) * ROWB) + (u32)((lane >> 4) * 16);
    u32 bRowSel = (u32)(((lane & 7) + ((lane >> 4) & 1) * 8) * ROWB)
                  + (u32)(((lane >> 3) & 1) * 16);

    // prologue: params(0) + gather(0) into A0
    m_params(blob, t, wb, bh, h, 0, 0);
    __syncthreads();
    m_gather(blob, xb, t, 0, 0);

#pragma unroll 1
    for (int kk = 0; kk < NKK; kk++) {
        // ---- stage B(kk): 64 o x 64 c fp16 (512 uint4) ----
        {
            const uint4* gh = (const uint4*)&g_wb[(size_t)kk * OO * CC];
#pragma unroll
            for (int it = 0; it < 4; it++) {
                int idx = it * 128 + t;
                int row = idx >> 3;
                int col = idx & 7;
                *(uint4*)(blob + M_OFF_B + row * ROWB + col * 16) = __ldg(&gh[idx]);
            }
        }
        // ---- params(kk+1) into alt slot ----
        if (kk < 8) m_params(blob, t, wb, bh, h, kk + 1, (kk + 1) & 1);
        __syncthreads();             // A[kk&1] (from prev iter), B(kk), params vis.
        // ---- gather(kk+1) into alt A buffer (LDGs lead; overlap MMA kk) ----
        if (kk < 8)
            m_gather(blob, xb, t, (kk + 1) & 1, (u32)(((kk + 1) & 1) * A_BYTES));
        // ---- MMA(kk) ----
        u32 aBase = S + (u32)((kk & 1) * A_BYTES) + aRow;
#pragma unroll
        for (int ks = 0; ks < 4; ks++) {
            u32 aa = aBase + ks * 32;
            u32 a0, a1, a2, a3;
            LDSM4(a0, a1, a2, a3, aa);
#pragma unroll
            for (int np = 0; np < 4; np++) {
                u32 ba = S + M_OFF_B + (u32)(np * 16 * ROWB) + bRowSel + ks * 32;
                u32 b0, b1, b2, b3;
                LDSM4(b0, b1, b2, b3, ba);
                mma16816(acc[np * 2 + 0], a0, a1, a2, a3, b0, b1);
                mma16816(acc[np * 2 + 1], a0, a1, a2, a3, b2, b3);
            }
        }
        __syncthreads();             // MMA(kk) + gather(kk+1) done
    }

    // ---- epilogue: stage D in smem [o][px] (pitch 68), coalesced write ----
    float* sD = (float*)blob;        // 64*68*4 = 17408 <= 31744
    {
        int px0 = warp * 16 + (lane >> 2);
#pragma unroll
        for (int j = 0; j < 8; j++) {
            int o = j * 8 + 2 * (lane & 3);
            sD[o * DPITCH + px0]           = acc[j][0];
            sD[(o + 1) * DPITCH + px0]     = acc[j][1];
            sD[o * DPITCH + px0 + 8]       = acc[j][2];
            sD[(o + 1) * DPITCH + px0 + 8] = acc[j][3];
        }
    }
    __syncthreads();
    {
        int o = t >> 1;
        int half = t & 1;
        float bv = __ldg(&bias[o]);
        size_t base = ((size_t)(b * OO + o) * HH + h) * WW + wb + half * 32;
        const float* src = &sD[o * DPITCH + half * 32];
#pragma unroll
        for (int i = 0; i < 8; i++) {
            float4 v = *(const float4*)&src[i * 4];
            v.x += bv; v.y += bv; v.z += bv; v.w += bv;
            *(float4*)&out[base + i * 4] = v;
        }
    }
}

// ============================================================
extern "C" void kernel_launch(void* const* d_in, const int* in_sizes, int n_in,
                              void* d_out, int out_size) {
    const float* x      = (const float*)d_in[0];
    const float* weight = (const float*)d_in[1];
    const float* bias   = (const float*)d_in[2];
    const float* pg_w   = (const float*)d_in[3];
    const float* pg_b   = (const float*)d_in[4];
    float* out = (float*)d_out;

    k_transpose_x<<<BB * HH, 256>>>(x);
    k_prep_w<<<(NKK * OO * CC + NKK * 32 * CC + 255) / 256, 256>>>(weight, pg_w);
    k_params<<<BB * HH * 2, 128>>>(pg_b);
    k_main<<<BB * HH * 2, 128>>>(bias, out);
}

// round 16
// speedup vs baseline: 1.3606x; 1.1607x over previous
#include <cuda_runtime.h>
#include <cuda_fp16.h>
#include <math.h>

#define BB 4
#define CC 64
#define HH 128
#define WW 128
#define OO 64
#define NKK 9
#define QDIM 576
#define NPIX (BB*HH*WW)     // 65536

typedef unsigned int u32;

// ---- device scratch ----
__device__ __half g_xh[BB*HH*WW*CC];            // NHWC x, fp16 (8.4 MB, L2-resident)
__device__ float g_params[27*NPIX];             // planar [co][pix]
__device__ __half g_wb[NKK*OO*CC];              // main weights fp16, [kk][o][c]
__device__ __half g_wpg[NKK*32*CC];             // pg weights fp16, [kk][co32][c]

__device__ __forceinline__ u32 smem_u32(const void* p) {
    u32 a;
    asm("{ .reg .u64 t; cvta.to.shared.u64 t, %1; cvt.u32.u64 %0, t; }" : "=r"(a) : "l"(p));
    return a;
}

#define LDSM4(r0, r1, r2, r3, addr) \
    asm volatile("ldmatrix.sync.aligned.m8n8.x4.shared.b16 {%0,%1,%2,%3},[%4];" \
        : "=r"(r0), "=r"(r1), "=r"(r2), "=r"(r3) : "r"(addr))

__device__ __forceinline__ void mma16816(float* d, u32 a0, u32 a1, u32 a2, u32 a3,
                                         u32 b0, u32 b1) {
    asm volatile(
        "mma.sync.aligned.m16n8k16.row.col.f32.f16.f16.f32 "
        "{%0,%1,%2,%3},{%4,%5,%6,%7},{%8,%9},{%0,%1,%2,%3};"
        : "+f"(d[0]), "+f"(d[1]), "+f"(d[2]), "+f"(d[3])
        : "r"(a0), "r"(a1), "r"(a2), "r"(a3), "r"(b0), "r"(b1));
}

__device__ __forceinline__ void h2_store(unsigned char* dst,
                                         float v0, float v1, float v2, float v3) {
    __half2 a = __floats2half2_rn(v0, v1);
    __half2 b = __floats2half2_rn(v2, v3);
    *(uint2*)dst = make_uint2(*(u32*)&a, *(u32*)&b);
}

// ============================================================
// Kernel 0: x NCHW -> NHWC fp16
// ============================================================
__global__ void k_transpose_x(const float* __restrict__ x) {
    __shared__ float tile[64][129];
    int bh = blockIdx.x;
    int b = bh >> 7, h = bh & 127;
    int t = threadIdx.x;
    for (int i = t; i < 64 * 128; i += 256) {
        int c = i >> 7, w = i & 127;
        tile[c][w] = x[((size_t)(b * CC + c) * HH + h) * WW + w];
    }
    __syncthreads();
    __half2* xh2 = (__half2*)g_xh;
    for (int i = t; i < 32 * 128; i += 256) {
        int c2 = i & 31, w = i >> 5;
        __half2 v = __floats2half2_rn(tile[c2 * 2][w], tile[c2 * 2 + 1][w]);
        xh2[((size_t)bh * WW + w) * 32 + c2] = v;
    }
}

// ============================================================
// Kernel 1: merged weight prep (fp16)
// ============================================================
__global__ void k_prep_w(const float* __restrict__ wgt,
                         const float* __restrict__ pgw) {
    int i = blockIdx.x * 256 + threadIdx.x;
    if (i < NKK * OO * CC) {                       // 36864
        int kk = i % 9;
        int c  = (i / 9) & 63;
        int o  = i / (9 * 64);
        g_wb[(kk * OO + o) * CC + c] = __float2half(wgt[i]);
    }
    int j = i - NKK * OO * CC;
    if (j >= 0 && j < NKK * 32 * CC) {             // 18432
        int c  = j & 63;
        int co = (j >> 6) & 31;
        int kk = j >> 11;
        float w = (co < 27) ? pgw[co * QDIM + c * 9 + kk] : 0.f;
        g_wpg[j] = __float2half(w);
    }
}

// ============================================================
// MMA constants
// ============================================================
#define APITCH 72                    // fp16/row (144 B)
#define ROWB (APITCH*2)              // 144
#define A_BYTES (64 * ROWB)          // 9216
#define DPITCH 68

// ============================================================
// Kernel 2: offset/mask conv (R12 structure; stage A = pure fp16 copy)
// smem: A@0 (9216), B@9216 (4608) -> 13824
// ============================================================
#define P_OFF_B 9216
#define P_SMEM  13824

__global__ void __launch_bounds__(128) k_params(const float* __restrict__ pgb) {
    __shared__ __align__(16) unsigned char blob[P_SMEM];
    u32 S = smem_u32(blob);
    int t = threadIdx.x;
    int lane = t & 31;
    int warp = t >> 5;
    int blk = blockIdx.x;            // 1024
    int wb = (blk & 1) * 64;
    int bh = blk >> 1;
    int b = bh >> 7, h = bh & 127;

    const __half* xh = &g_xh[(size_t)b * HH * WW * CC];

    float acc[4][4];
#pragma unroll
    for (int j = 0; j < 4; j++)
#pragma unroll
        for (int r = 0; r < 4; r++) acc[j][r] = 0.f;

    u32 aRow = (u32)((warp * 16 + (lane & 15)) * ROWB) + (u32)((lane >> 4) * 16);
    u32 bRowSel = (u32)(((lane & 7) + ((lane >> 4) & 1) * 8) * ROWB)
                  + (u32)(((lane >> 3) & 1) * 16);

#pragma unroll 1
    for (int kk = 0; kk < NKK; kk++) {
        int dh = kk / 3 - 1, dw = kk % 3 - 1;
        int hh = h + dh;
        __syncthreads();             // prev MMA reads done
        // ---- stage A: shifted patch 64 px x 64 c, fp16 copy (uint4) ----
#pragma unroll
        for (int it = 0; it < 4; it++) {
            int idx = it * 128 + t;
            int c8 = idx & 7;
            int px = idx >> 3;
            int gw = wb + px + dw;
            uint4 g = make_uint4(0, 0, 0, 0);
            if (hh >= 0 && hh < HH && gw >= 0 && gw < WW)
                g = __ldg((const uint4*)(xh + ((size_t)hh * WW + gw) * CC) + c8);
            *(uint4*)(blob + px * ROWB + c8 * 16) = g;
        }
        // ---- stage B: 32 co x 64 c fp16 (256 uint4) ----
        {
            const uint4* gh = (const uint4*)&g_wpg[(size_t)kk * 32 * CC];
#pragma unroll
            for (int it = 0; it < 2; it++) {
                int idx = it * 128 + t;
                int row = idx >> 3;
                int col = idx & 7;
                *(uint4*)(blob + P_OFF_B + row * ROWB + col * 16) = __ldg(&gh[idx]);
            }
        }
        __syncthreads();
        // ---- MMA: 4 ksteps x 2 n-pairs ----
#pragma unroll
        for (int ks = 0; ks < 4; ks++) {
            u32 aa = S + aRow + ks * 32;
            u32 a0, a1, a2, a3;
            LDSM4(a0, a1, a2, a3, aa);
#pragma unroll
            for (int np = 0; np < 2; np++) {
                u32 ba = S + P_OFF_B + (u32)(np * 16 * ROWB) + bRowSel + ks * 32;
                u32 b0, b1, b2, b3;
                LDSM4(b0, b1, b2, b3, ba);
                mma16816(acc[np * 2 + 0], a0, a1, a2, a3, b0, b1);
                mma16816(acc[np * 2 + 1], a0, a1, a2, a3, b2, b3);
            }
        }
    }

    // ---- epilogue: stage sD[32co][68px], planar coalesced write ----
    __syncthreads();
    float* sD = (float*)blob;
    {
        int px0 = warp * 16 + (lane >> 2);
#pragma unroll
        for (int j = 0; j < 4; j++) {
            int co = j * 8 + 2 * (lane & 3);
            sD[co * DPITCH + px0]           = acc[j][0];
            sD[(co + 1) * DPITCH + px0]     = acc[j][1];
            sD[co * DPITCH + px0 + 8]       = acc[j][2];
            sD[(co + 1) * DPITCH + px0 + 8] = acc[j][3];
        }
    }
    __syncthreads();
#pragma unroll
    for (int i = 0; i < 14; i++) {
        int idx = i * 128 + t;               // 27*64 = 1728
        if (idx < 1728) {
            int co = idx >> 6;
            int px = idx & 63;
            g_params[(size_t)co * NPIX + (size_t)bh * WW + wb + px] =
                sD[co * DPITCH + px] + __ldg(&pgb[co]);
        }
    }
}

// ============================================================
// Kernel 3: fused gather + MMA (R13 pipeline; fp16 source loads)
// smem: A0@0, A1@9216, B@18432 (9216), pw@27648 [2][4][64],
//       pi@29696 [2][4][64] -> 31744
// ============================================================
#define M_OFF_B  18432
#define M_OFF_PW 27648
#define M_OFF_PI 29696
#define M_SMEM   31744

__device__ __forceinline__ void m_params(unsigned char* blob, int t, int wb,
                                         int bh, int h, int kt, int slot) {
    if (t >= 64) return;
    float* pw = (float*)(blob + M_OFF_PW) + slot * 256;
    int*   pi = (int*)(blob + M_OFF_PI) + slot * 256;
    int px = t;
    int w = wb + px;
    size_t pixi = (size_t)bh * WW + w;
    float dy = __ldg(&g_params[(size_t)(2 * kt) * NPIX + pixi]);
    float dx = __ldg(&g_params[(size_t)(2 * kt + 1) * NPIX + pixi]);
    float m  = __ldg(&g_params[(size_t)(18 + kt) * NPIX + pixi]);
    float mask = 1.f / (1.f + expf(-m));
    float ys = (float)(h - 1 + kt / 3) + dy;
    float xs = (float)(w - 1 + kt % 3) + dx;
    float y0f = floorf(ys), x0f = floorf(xs);
    float ly = ys - y0f, lx = xs - x0f;
    int y0 = (int)y0f, x0 = (int)x0f;
    float vy0 = (y0 >= 0 && y0 < HH) ? 1.f : 0.f;
    float vy1 = (y0 + 1 >= 0 && y0 + 1 < HH) ? 1.f : 0.f;
    float vx0 = (x0 >= 0 && x0 < WW) ? 1.f : 0.f;
    float vx1 = (x0 + 1 >= 0 && x0 + 1 < WW) ? 1.f : 0.f;
    pw[0 * 64 + px] = (1.f - ly) * (1.f - lx) * mask * vy0 * vx0;
    pw[1 * 64 + px] = (1.f - ly) * lx         * mask * vy0 * vx1;
    pw[2 * 64 + px] = ly * (1.f - lx)         * mask * vy1 * vx0;
    pw[3 * 64 + px] = ly * lx                 * mask * vy1 * vx1;
    pi[0 * 64 + px] = min(max(y0, 0), HH - 1) * WW;
    pi[1 * 64 + px] = min(max(y0 + 1, 0), HH - 1) * WW;
    pi[2 * 64 + px] = min(max(x0, 0), WW - 1);
    pi[3 * 64 + px] = min(max(x0 + 1, 0), WW - 1);
}

__device__ __forceinline__ void m_gather(unsigned char* blob, const __half* xh,
                                         int t, int slot, u32 aOff) {
    const float* pw = (const float*)(blob + M_OFF_PW) + slot * 256;
    const int*   pi = (const int*)(blob + M_OFF_PI) + slot * 256;
#pragma unroll
    for (int it = 0; it < 8; it++) {
        int idx = it * 128 + t;
        int c4 = idx & 15;
        int px = idx >> 4;
        float w00 = pw[0 * 64 + px];
        float w01 = pw[1 * 64 + px];
        float w10 = pw[2 * 64 + px];
        float w11 = pw[3 * 64 + px];
        int r0  = pi[0 * 64 + px];
        int r1  = pi[1 * 64 + px];
        int x0c = pi[2 * 64 + px];
        int x1c = pi[3 * 64 + px];
        uint2 u00 = __ldg((const uint2*)(xh + (size_t)(r0 + x0c) * CC) + c4);
        uint2 u01 = __ldg((const uint2*)(xh + (size_t)(r0 + x1c) * CC) + c4);
        uint2 u10 = __ldg((const uint2*)(xh + (size_t)(r1 + x0c) * CC) + c4);
        uint2 u11 = __ldg((const uint2*)(xh + (size_t)(r1 + x1c) * CC) + c4);
        float2 a00 = __half22float2(*(__half2*)&u00.x);
        float2 b00 = __half22float2(*(__half2*)&u00.y);
        float2 a01 = __half22float2(*(__half2*)&u01.x);
        float2 b01 = __half22float2(*(__half2*)&u01.y);
        float2 a10 = __half22float2(*(__half2*)&u10.x);
        float2 b10 = __half22float2(*(__half2*)&u10.y);
        float2 a11 = __half22float2(*(__half2*)&u11.x);
        float2 b11 = __half22float2(*(__half2*)&u11.y);
        float v0 = w00 * a00.x + w01 * a01.x + w10 * a10.x + w11 * a11.x;
        float v1 = w00 * a00.y + w01 * a01.y + w10 * a10.y + w11 * a11.y;
        float v2 = w00 * b00.x + w01 * b01.x + w10 * b10.x + w11 * b11.x;
        float v3 = w00 * b00.y + w01 * b01.y + w10 * b10.y + w11 * b11.y;
        h2_store(blob + aOff + px * ROWB + c4 * 8, v0, v1, v2, v3);
    }
}

__global__ void __launch_bounds__(128) k_main(const float* __restrict__ bias,
                                              float* __restrict__ out) {
    __shared__ __align__(16) unsigned char blob[M_SMEM];
    u32 S = smem_u32(blob);

    int t = threadIdx.x;
    int lane = t & 31;
    int warp = t >> 5;
    int blk = blockIdx.x;
    int wb = (blk & 1) * 64;
    int bh = blk >> 1;
    int b = bh >> 7, h = bh & 127;

    const __half* xh = &g_xh[(size_t)b * HH * WW * CC];

    float acc[8][4];
#pragma unroll
    for (int j = 0; j < 8; j++)
#pragma unroll
        for (int r = 0; r < 4; r++) acc[j][r] = 0.f;

    u32 aRow = (u32)((warp * 16 + (lane & 15)) * ROWB) + (u32)((lane >> 4) * 16);
    u32 bRowSel = (u32)(((lane & 7) + ((lane >> 4) & 1) * 8) * ROWB)
                  + (u32)(((lane >> 3) & 1) * 16);

    // prologue: params(0) + gather(0) into A0
    m_params(blob, t, wb, bh, h, 0, 0);
    __syncthreads();
    m_gather(blob, xh, t, 0, 0);

#pragma unroll 1
    for (int kk = 0; kk < NKK; kk++) {
        // ---- stage B(kk): 64 o x 64 c fp16 (512 uint4) ----
        {
            const uint4* gh = (const uint4*)&g_wb[(size_t)kk * OO * CC];
#pragma unroll
            for (int it = 0; it < 4; it++) {
                int idx = it * 128 + t;
                int row = idx >> 3;
                int col = idx & 7;
                *(uint4*)(blob + M_OFF_B + row * ROWB + col * 16) = __ldg(&gh[idx]);
            }
        }
        // ---- params(kk+1) into alt slot ----
        if (kk < 8) m_params(blob, t, wb, bh, h, kk + 1, (kk + 1) & 1);
        __syncthreads();             // A[kk&1] (from prev iter), B(kk), params vis.
        // ---- gather(kk+1) into alt A buffer (LDGs lead; overlap MMA kk) ----
        if (kk < 8)
            m_gather(blob, xh, t, (kk + 1) & 1, (u32)(((kk + 1) & 1) * A_BYTES));
        // ---- MMA(kk) ----
        u32 aBase = S + (u32)((kk & 1) * A_BYTES) + aRow;
#pragma unroll
        for (int ks = 0; ks < 4; ks++) {
            u32 aa = aBase + ks * 32;
            u32 a0, a1, a2, a3;
            LDSM4(a0, a1, a2, a3, aa);
#pragma unroll
            for (int np = 0; np < 4; np++) {
                u32 ba = S + M_OFF_B + (u32)(np * 16 * ROWB) + bRowSel + ks * 32;
                u32 b0, b1, b2, b3;
                LDSM4(b0, b1, b2, b3, ba);
                mma16816(acc[np * 2 + 0], a0, a1, a2, a3, b0, b1);
                mma16816(acc[np * 2 + 1], a0, a1, a2, a3, b2, b3);
            }
        }
        __syncthreads();             // MMA(kk) + gather(kk+1) done
    }

    // ---- epilogue: stage D in smem [o][px] (pitch 68), coalesced write ----
    float* sD = (float*)blob;        // 64*68*4 = 17408 <= 31744
    {
        int px0 = warp * 16 + (lane >> 2);
#pragma unroll
        for (int j = 0; j < 8; j++) {
            int o = j * 8 + 2 * (lane & 3);
            sD[o * DPITCH + px0]           = acc[j][0];
            sD[(o + 1) * DPITCH + px0]     = acc[j][1];
            sD[o * DPITCH + px0 + 8]       = acc[j][2];
            sD[(o + 1) * DPITCH + px0 + 8] = acc[j][3];
        }
    }
    __syncthreads();
    {
        int o = t >> 1;
        int half = t & 1;
        float bv = __ldg(&bias[o]);
        size_t base = ((size_t)(b * OO + o) * HH + h) * WW + wb + half * 32;
        const float* src = &sD[o * DPITCH + half * 32];
#pragma unroll
        for (int i = 0; i < 8; i++) {
            float4 v = *(const float4*)&src[i * 4];
            v.x += bv; v.y += bv; v.z += bv; v.w += bv;
            *(float4*)&out[base + i * 4] = v;
        }
    }
}

// ============================================================
extern "C" void kernel_launch(void* const* d_in, const int* in_sizes, int n_in,
                              void* d_out, int out_size) {
    const float* x      = (const float*)d_in[0];
    const float* weight = (const float*)d_in[1];
    const float* bias   = (const float*)d_in[2];
    const float* pg_w   = (const float*)d_in[3];
    const float* pg_b   = (const float*)d_in[4];
    float* out = (float*)d_out;

    k_transpose_x<<<BB * HH, 256>>>(x);
    k_prep_w<<<(NKK * OO * CC + NKK * 32 * CC + 255) / 256, 256>>>(weight, pg_w);
    k_params<<<BB * HH * 2, 128>>>(pg_b);
    k_main<<<BB * HH * 2, 128>>>(bias, out);
}

// round 17
// speedup vs baseline: 1.4724x; 1.0822x over previous
#include <cuda_runtime.h>
#include <cuda_fp16.h>
#include <math.h>

#define BB 4
#define CC 64
#define HH 128
#define WW 128
#define OO 64
#define NKK 9
#define QDIM 576
#define NPIX (BB*HH*WW)     // 65536

typedef unsigned int u32;

// ---- device scratch ----
__device__ __half g_xh[BB*HH*WW*CC];            // NHWC x, fp16
__device__ float g_params[27*NPIX];             // planar [co][pix]
__device__ __half g_wb[NKK*OO*CC];              // main weights fp16, [kk][o][c]
__device__ __half g_wpg[NKK*32*CC];             // pg weights fp16, [kk][co32][c]

__device__ __forceinline__ u32 smem_u32(const void* p) {
    u32 a;
    asm("{ .reg .u64 t; cvta.to.shared.u64 t, %1; cvt.u32.u64 %0, t; }" : "=r"(a) : "l"(p));
    return a;
}

#define LDSM4(r0, r1, r2, r3, addr) \
    asm volatile("ldmatrix.sync.aligned.m8n8.x4.shared.b16 {%0,%1,%2,%3},[%4];" \
        : "=r"(r0), "=r"(r1), "=r"(r2), "=r"(r3) : "r"(addr))

__device__ __forceinline__ void mma16816(float* d, u32 a0, u32 a1, u32 a2, u32 a3,
                                         u32 b0, u32 b1) {
    asm volatile(
        "mma.sync.aligned.m16n8k16.row.col.f32.f16.f16.f32 "
        "{%0,%1,%2,%3},{%4,%5,%6,%7},{%8,%9},{%0,%1,%2,%3};"
        : "+f"(d[0]), "+f"(d[1]), "+f"(d[2]), "+f"(d[3])
        : "r"(a0), "r"(a1), "r"(a2), "r"(a3), "r"(b0), "r"(b1));
}

// ============================================================
// Kernel 0: x NCHW -> NHWC fp16
// ============================================================
__global__ void k_transpose_x(const float* __restrict__ x) {
    __shared__ float tile[64][129];
    int bh = blockIdx.x;
    int b = bh >> 7, h = bh & 127;
    int t = threadIdx.x;
    for (int i = t; i < 64 * 128; i += 256) {
        int c = i >> 7, w = i & 127;
        tile[c][w] = x[((size_t)(b * CC + c) * HH + h) * WW + w];
    }
    __syncthreads();
    __half2* xh2 = (__half2*)g_xh;
    for (int i = t; i < 32 * 128; i += 256) {
        int c2 = i & 31, w = i >> 5;
        __half2 v = __floats2half2_rn(tile[c2 * 2][w], tile[c2 * 2 + 1][w]);
        xh2[((size_t)bh * WW + w) * 32 + c2] = v;
    }
}

// ============================================================
// Kernel 1: merged weight prep (fp16)
// ============================================================
__global__ void k_prep_w(const float* __restrict__ wgt,
                         const float* __restrict__ pgw) {
    int i = blockIdx.x * 256 + threadIdx.x;
    if (i < NKK * OO * CC) {                       // 36864
        int kk = i % 9;
        int c  = (i / 9) & 63;
        int o  = i / (9 * 64);
        g_wb[(kk * OO + o) * CC + c] = __float2half(wgt[i]);
    }
    int j = i - NKK * OO * CC;
    if (j >= 0 && j < NKK * 32 * CC) {             // 18432
        int c  = j & 63;
        int co = (j >> 6) & 31;
        int kk = j >> 11;
        float w = (co < 27) ? pgw[co * QDIM + c * 9 + kk] : 0.f;
        g_wpg[j] = __float2half(w);
    }
}

// ============================================================
// MMA constants
// ============================================================
#define APITCH 72                    // fp16/row (144 B)
#define ROWB (APITCH*2)              // 144
#define A_BYTES (64 * ROWB)          // 9216
#define DPITCH 68

// ============================================================
// Kernel 2: offset/mask conv (R16 exact)
// smem: A@0 (9216), B@9216 (4608) -> 13824
// ============================================================
#define P_OFF_B 9216
#define P_SMEM  13824

__global__ void __launch_bounds__(128) k_params(const float* __restrict__ pgb) {
    __shared__ __align__(16) unsigned char blob[P_SMEM];
    u32 S = smem_u32(blob);
    int t = threadIdx.x;
    int lane = t & 31;
    int warp = t >> 5;
    int blk = blockIdx.x;            // 1024
    int wb = (blk & 1) * 64;
    int bh = blk >> 1;
    int b = bh >> 7, h = bh & 127;

    const __half* xh = &g_xh[(size_t)b * HH * WW * CC];

    float acc[4][4];
#pragma unroll
    for (int j = 0; j < 4; j++)
#pragma unroll
        for (int r = 0; r < 4; r++) acc[j][r] = 0.f;

    u32 aRow = (u32)((warp * 16 + (lane & 15)) * ROWB) + (u32)((lane >> 4) * 16);
    u32 bRowSel = (u32)(((lane & 7) + ((lane >> 4) & 1) * 8) * ROWB)
                  + (u32)(((lane >> 3) & 1) * 16);

#pragma unroll 1
    for (int kk = 0; kk < NKK; kk++) {
        int dh = kk / 3 - 1, dw = kk % 3 - 1;
        int hh = h + dh;
        __syncthreads();             // prev MMA reads done
        // ---- stage A: shifted patch 64 px x 64 c, fp16 copy (uint4) ----
#pragma unroll
        for (int it = 0; it < 4; it++) {
            int idx = it * 128 + t;
            int c8 = idx & 7;
            int px = idx >> 3;
            int gw = wb + px + dw;
            uint4 g = make_uint4(0, 0, 0, 0);
            if (hh >= 0 && hh < HH && gw >= 0 && gw < WW)
                g = __ldg((const uint4*)(xh + ((size_t)hh * WW + gw) * CC) + c8);
            *(uint4*)(blob + px * ROWB + c8 * 16) = g;
        }
        // ---- stage B: 32 co x 64 c fp16 (256 uint4) ----
        {
            const uint4* gh = (const uint4*)&g_wpg[(size_t)kk * 32 * CC];
#pragma unroll
            for (int it = 0; it < 2; it++) {
                int idx = it * 128 + t;
                int row = idx >> 3;
                int col = idx & 7;
                *(uint4*)(blob + P_OFF_B + row * ROWB + col * 16) = __ldg(&gh[idx]);
            }
        }
        __syncthreads();
        // ---- MMA: 4 ksteps x 2 n-pairs ----
#pragma unroll
        for (int ks = 0; ks < 4; ks++) {
            u32 aa = S + aRow + ks * 32;
            u32 a0, a1, a2, a3;
            LDSM4(a0, a1, a2, a3, aa);
#pragma unroll
            for (int np = 0; np < 2; np++) {
                u32 ba = S + P_OFF_B + (u32)(np * 16 * ROWB) + bRowSel + ks * 32;
                u32 b0, b1, b2, b3;
                LDSM4(b0, b1, b2, b3, ba);
                mma16816(acc[np * 2 + 0], a0, a1, a2, a3, b0, b1);
                mma16816(acc[np * 2 + 1], a0, a1, a2, a3, b2, b3);
            }
        }
    }

    // ---- epilogue: stage sD[32co][68px], planar coalesced write ----
    __syncthreads();
    float* sD = (float*)blob;
    {
        int px0 = warp * 16 + (lane >> 2);
#pragma unroll
        for (int j = 0; j < 4; j++) {
            int co = j * 8 + 2 * (lane & 3);
            sD[co * DPITCH + px0]           = acc[j][0];
            sD[(co + 1) * DPITCH + px0]     = acc[j][1];
            sD[co * DPITCH + px0 + 8]       = acc[j][2];
            sD[(co + 1) * DPITCH + px0 + 8] = acc[j][3];
        }
    }
    __syncthreads();
#pragma unroll
    for (int i = 0; i < 14; i++) {
        int idx = i * 128 + t;               // 27*64 = 1728
        if (idx < 1728) {
            int co = idx >> 6;
            int px = idx & 63;
            g_params[(size_t)co * NPIX + (size_t)bh * WW + wb + px] =
                sD[co * DPITCH + px] + __ldg(&pgb[co]);
        }
    }
}

// ============================================================
// Kernel 3: fused gather + MMA. 2M x 2N warp tiling, uint4 gather.
// smem: A0@0, A1@9216, B@18432 (9216), pw@27648 [2][4][64],
//       pi@29696 [2][4][64] -> 31744
// ============================================================
#define M_OFF_B  18432
#define M_OFF_PW 27648
#define M_OFF_PI 29696
#define M_SMEM   31744

__device__ __forceinline__ void m_params(unsigned char* blob, int t, int wb,
                                         int bh, int h, int kt, int slot) {
    if (t >= 64) return;
    float* pw = (float*)(blob + M_OFF_PW) + slot * 256;
    int*   pi = (int*)(blob + M_OFF_PI) + slot * 256;
    int px = t;
    int w = wb + px;
    size_t pixi = (size_t)bh * WW + w;
    float dy = __ldg(&g_params[(size_t)(2 * kt) * NPIX + pixi]);
    float dx = __ldg(&g_params[(size_t)(2 * kt + 1) * NPIX + pixi]);
    float m  = __ldg(&g_params[(size_t)(18 + kt) * NPIX + pixi]);
    float mask = 1.f / (1.f + expf(-m));
    float ys = (float)(h - 1 + kt / 3) + dy;
    float xs = (float)(w - 1 + kt % 3) + dx;
    float y0f = floorf(ys), x0f = floorf(xs);
    float ly = ys - y0f, lx = xs - x0f;
    int y0 = (int)y0f, x0 = (int)x0f;
    float vy0 = (y0 >= 0 && y0 < HH) ? 1.f : 0.f;
    float vy1 = (y0 + 1 >= 0 && y0 + 1 < HH) ? 1.f : 0.f;
    float vx0 = (x0 >= 0 && x0 < WW) ? 1.f : 0.f;
    float vx1 = (x0 + 1 >= 0 && x0 + 1 < WW) ? 1.f : 0.f;
    pw[0 * 64 + px] = (1.f - ly) * (1.f - lx) * mask * vy0 * vx0;
    pw[1 * 64 + px] = (1.f - ly) * lx         * mask * vy0 * vx1;
    pw[2 * 64 + px] = ly * (1.f - lx)         * mask * vy1 * vx0;
    pw[3 * 64 + px] = ly * lx                 * mask * vy1 * vx1;
    pi[0 * 64 + px] = min(max(y0, 0), HH - 1) * WW;
    pi[1 * 64 + px] = min(max(y0 + 1, 0), HH - 1) * WW;
    pi[2 * 64 + px] = min(max(x0, 0), WW - 1);
    pi[3 * 64 + px] = min(max(x0 + 1, 0), WW - 1);
}

__device__ __forceinline__ void m_gather(unsigned char* blob, const __half* xh,
                                         int t, int slot, u32 aOff) {
    const float* pw = (const float*)(blob + M_OFF_PW) + slot * 256;
    const int*   pi = (const int*)(blob + M_OFF_PI) + slot * 256;
#pragma unroll
    for (int it = 0; it < 4; it++) {
        int idx = it * 128 + t;
        int c8 = idx & 7;
        int px = idx >> 3;
        float w00 = pw[0 * 64 + px];
        float w01 = pw[1 * 64 + px];
        float w10 = pw[2 * 64 + px];
        float w11 = pw[3 * 64 + px];
        int r0  = pi[0 * 64 + px];
        int r1  = pi[1 * 64 + px];
        int x0c = pi[2 * 64 + px];
        int x1c = pi[3 * 64 + px];
        uint4 u00 = __ldg((const uint4*)(xh + (size_t)(r0 + x0c) * CC) + c8);
        uint4 u01 = __ldg((const uint4*)(xh + (size_t)(r0 + x1c) * CC) + c8);
        uint4 u10 = __ldg((const uint4*)(xh + (size_t)(r1 + x0c) * CC) + c8);
        uint4 u11 = __ldg((const uint4*)(xh + (size_t)(r1 + x1c) * CC) + c8);
        uint4 outw;
        const u32* p00 = &u00.x; const u32* p01 = &u01.x;
        const u32* p10 = &u10.x; const u32* p11 = &u11.x;
        u32* po = &outw.x;
#pragma unroll
        for (int wd = 0; wd < 4; wd++) {
            float2 a = __half22float2(*(__half2*)&p00[wd]);
            float2 bb = __half22float2(*(__half2*)&p01[wd]);
            float2 cc = __half22float2(*(__half2*)&p10[wd]);
            float2 dd = __half22float2(*(__half2*)&p11[wd]);
            float v0 = w00 * a.x + w01 * bb.x + w10 * cc.x + w11 * dd.x;
            float v1 = w00 * a.y + w01 * bb.y + w10 * cc.y + w11 * dd.y;
            __half2 hv = __floats2half2_rn(v0, v1);
            po[wd] = *(u32*)&hv;
        }
        *(uint4*)(blob + aOff + px * ROWB + c8 * 16) = outw;
    }
}

__global__ void __launch_bounds__(128) k_main(const float* __restrict__ bias,
                                              float* __restrict__ out) {
    __shared__ __align__(16) unsigned char blob[M_SMEM];
    u32 S = smem_u32(blob);

    int t = threadIdx.x;
    int lane = t & 31;
    int warp = t >> 5;
    int mg = warp & 1;               // px half: mg*32
    int ng = warp >> 1;              // o half: ng*32
    int blk = blockIdx.x;
    int wb = (blk & 1) * 64;
    int bh = blk >> 1;
    int b = bh >> 7, h = bh & 127;

    const __half* xh = &g_xh[(size_t)b * HH * WW * CC];

    float acc[8][4];                 // [at*4 + np*2 + j][4]
#pragma unroll
    for (int j = 0; j < 8; j++)
#pragma unroll
        for (int r = 0; r < 4; r++) acc[j][r] = 0.f;

    u32 aRow0 = (u32)((mg * 32 + 0  + (lane & 15)) * ROWB) + (u32)((lane >> 4) * 16);
    u32 aRow1 = (u32)((mg * 32 + 16 + (lane & 15)) * ROWB) + (u32)((lane >> 4) * 16);
    u32 bRowSel = (u32)(((lane & 7) + ((lane >> 4) & 1) * 8) * ROWB)
                  + (u32)(((lane >> 3) & 1) * 16);

    // prologue: params(0) + gather(0) into A0
    m_params(blob, t, wb, bh, h, 0, 0);
    __syncthreads();
    m_gather(blob, xh, t, 0, 0);

#pragma unroll 1
    for (int kk = 0; kk < NKK; kk++) {
        // ---- stage B(kk): 64 o x 64 c fp16 (512 uint4) ----
        {
            const uint4* gh = (const uint4*)&g_wb[(size_t)kk * OO * CC];
#pragma unroll
            for (int it = 0; it < 4; it++) {
                int idx = it * 128 + t;
                int row = idx >> 3;
                int col = idx & 7;
                *(uint4*)(blob + M_OFF_B + row * ROWB + col * 16) = __ldg(&gh[idx]);
            }
        }
        // ---- params(kk+1) into alt slot ----
        if (kk < 8) m_params(blob, t, wb, bh, h, kk + 1, (kk + 1) & 1);
        __syncthreads();             // A[kk&1], B(kk), params visible
        // ---- gather(kk+1) into alt A buffer (LDGs lead; overlap MMA kk) ----
        if (kk < 8)
            m_gather(blob, xh, t, (kk + 1) & 1, (u32)(((kk + 1) & 1) * A_BYTES));
        // ---- MMA(kk): this warp 32 px x 32 o ----
        u32 aBase = S + (u32)((kk & 1) * A_BYTES);
#pragma unroll
        for (int ks = 0; ks < 4; ks++) {
            u32 a0, a1, a2, a3, a4, a5, a6, a7;
            LDSM4(a0, a1, a2, a3, aBase + aRow0 + ks * 32);
            LDSM4(a4, a5, a6, a7, aBase + aRow1 + ks * 32);
#pragma unroll
            for (int np = 0; np < 2; np++) {
                u32 ba = S + M_OFF_B + (u32)((ng * 2 + np) * 16 * ROWB) + bRowSel + ks * 32;
                u32 b0, b1, b2, b3;
                LDSM4(b0, b1, b2, b3, ba);
                mma16816(acc[0 * 4 + np * 2 + 0], a0, a1, a2, a3, b0, b1);
                mma16816(acc[0 * 4 + np * 2 + 1], a0, a1, a2, a3, b2, b3);
                mma16816(acc[1 * 4 + np * 2 + 0], a4, a5, a6, a7, b0, b1);
                mma16816(acc[1 * 4 + np * 2 + 1], a4, a5, a6, a7, b2, b3);
            }
        }
        __syncthreads();             // MMA(kk) + gather(kk+1) done
    }

    // ---- epilogue: stage D in smem [o][px] (pitch 68), coalesced write ----
    float* sD = (float*)blob;        // 64*68*4 = 17408 <= 31744
#pragma unroll
    for (int at = 0; at < 2; at++) {
        int px0 = mg * 32 + at * 16 + (lane >> 2);
#pragma unroll
        for (int np = 0; np < 2; np++) {
#pragma unroll
            for (int j = 0; j < 2; j++) {
                int o = ng * 32 + np * 16 + j * 8 + 2 * (lane & 3);
                float* a4 = acc[at * 4 + np * 2 + j];
                sD[o * DPITCH + px0]           = a4[0];
                sD[(o + 1) * DPITCH + px0]     = a4[1];
                sD[o * DPITCH + px0 + 8]       = a4[2];
                sD[(o + 1) * DPITCH + px0 + 8] = a4[3];
            }
        }
    }
    __syncthreads();
    {
        int o = t >> 1;
        int half = t & 1;
        float bv = __ldg(&bias[o]);
        size_t base = ((size_t)(b * OO + o) * HH + h) * WW + wb + half * 32;
        const float* src = &sD[o * DPITCH + half * 32];
#pragma unroll
        for (int i = 0; i < 8; i++) {
            float4 v = *(const float4*)&src[i * 4];
            v.x += bv; v.y += bv; v.z += bv; v.w += bv;
            *(float4*)&out[base + i * 4] = v;
        }
    }
}

// ============================================================
extern "C" void kernel_launch(void* const* d_in, const int* in_sizes, int n_in,
                              void* d_out, int out_size) {
    const float* x      = (const float*)d_in[0];
    const float* weight = (const float*)d_in[1];
    const float* bias   = (const float*)d_in[2];
    const float* pg_w   = (const float*)d_in[3];
    const float* pg_b   = (const float*)d_in[4];
    float* out = (float*)d_out;

    k_transpose_x<<<BB * HH, 256>>>(x);
    k_prep_w<<<(NKK * OO * CC + NKK * 32 * CC + 255) / 256, 256>>>(weight, pg_w);
    k_params<<<BB * HH * 2, 128>>>(pg_b);
    k_main<<<BB * HH * 2, 128>>>(bias, out);
}